// round 7
// baseline (speedup 1.0000x reference)
#include <cuda_runtime.h>
#include <math.h>

#define NH 12
#define NB 2
#define SQ 1024
#define DM 768
#define DK 64
#define NKEYS 32
#define NBH (NB*NH)            // 24
#define NROWS (NBH*SQ)         // 24576
#define NTOT (NBH*SQ*SQ)       // 25165824

// ---- scratch (static __device__ arrays; no allocation allowed) ----
__device__ uint4    g_keys[NKEYS];
__device__ float    g_q[NBH*SQ*DK];
__device__ float    g_k[NBH*SQ*DK];
__device__ float    g_v[NBH*SQ*DK];
__device__ float    g_w[NTOT];          // sampled-average weights
__device__ unsigned g_rowsum[NROWS];    // integer draw counts per row
__device__ float    g_scale[NROWS];
__device__ float    g_attn[NBH*SQ*DK];

__device__ __forceinline__ unsigned rotl32(unsigned x, int r) {
    return __funnelshift_l(x, x, r);
}

#define R1(x0,x1,r) { x0 += x1; x1 = rotl32(x1,(r)) ^ x0; }

// Threefry-2x32, 20 rounds, key injections merged into the following round's
// add (IADD3-friendly). Caller passes x0 = k0, x1 = ctr + k1.
__device__ __forceinline__ void tf_block(unsigned& x0, unsigned& x1,
                                         unsigned k0, unsigned k1, unsigned k2) {
    R1(x0,x1,13) R1(x0,x1,15) R1(x0,x1,26) R1(x0,x1,6)
    x1 += k2 + 1u; x0 += k1 + x1; x1 = rotl32(x1,17) ^ x0;
    R1(x0,x1,29) R1(x0,x1,16) R1(x0,x1,24)
    x1 += k0 + 2u; x0 += k2 + x1; x1 = rotl32(x1,13) ^ x0;
    R1(x0,x1,15) R1(x0,x1,26) R1(x0,x1,6)
    x1 += k1 + 3u; x0 += k0 + x1; x1 = rotl32(x1,17) ^ x0;
    R1(x0,x1,29) R1(x0,x1,16) R1(x0,x1,24)
    x1 += k2 + 4u; x0 += k1 + x1; x1 = rotl32(x1,13) ^ x0;
    R1(x0,x1,15) R1(x0,x1,26) R1(x0,x1,6)
    x0 += k2; x1 += k0 + 5u;
}

// ---- setup: zero rowsums; block 0 derives the 32 child keys ----
// child_k = threefry2x32(parent=(0,42), x0=hi=0, x1=lo=k)  [partitionable split]
__global__ void k_setup() {
    int idx = blockIdx.x * 256 + threadIdx.x;
    if (idx < NROWS) g_rowsum[idx] = 0u;
    if (blockIdx.x == 0 && threadIdx.x < NKEYS) {
        unsigned k0 = 0u, k1 = 42u;
        unsigned k2 = k0 ^ k1 ^ 0x1BD11BDAu;
        unsigned x0 = k0, x1 = threadIdx.x + k1;
        tf_block(x0, x1, k0, k1, k2);
        g_keys[threadIdx.x] = make_uint4(x0, x1, x0 ^ x1 ^ 0x1BD11BDAu, 0u);
    }
}

// ---- fused QKV projection: z=0/1/2 -> Q/K/V; C[b,h,s,d] scatter ----
__global__ void k_qkv3(const float* __restrict__ X,
                       const float* __restrict__ Wq, const float* __restrict__ bq,
                       const float* __restrict__ Wk, const float* __restrict__ bk,
                       const float* __restrict__ Wv, const float* __restrict__ bv) {
    __shared__ float As[16][65];
    __shared__ float Bs[16][65];
    int which = blockIdx.z;
    const float* W    = (which == 0) ? Wq : ((which == 1) ? Wk : Wv);
    const float* bias = (which == 0) ? bq : ((which == 1) ? bk : bv);
    float* C          = (which == 0) ? g_q : ((which == 1) ? g_k : g_v);
    int tid = threadIdx.x;
    int tx = tid & 15, ty = tid >> 4;
    int m0 = blockIdx.y * 64, n0 = blockIdx.x * 64;
    int lr = tid >> 2;           // 0..63
    int lc = (tid & 3) << 2;     // 0,4,8,12
    float acc[4][4] = {};
    for (int kb = 0; kb < DM; kb += 16) {
        float4 a4 = *(const float4*)(X + (size_t)(m0 + lr) * DM + kb + lc);
        float4 b4 = *(const float4*)(W + (size_t)(n0 + lr) * DM + kb + lc);
        As[lc+0][lr] = a4.x; As[lc+1][lr] = a4.y; As[lc+2][lr] = a4.z; As[lc+3][lr] = a4.w;
        Bs[lc+0][lr] = b4.x; Bs[lc+1][lr] = b4.y; Bs[lc+2][lr] = b4.z; Bs[lc+3][lr] = b4.w;
        __syncthreads();
        #pragma unroll
        for (int kk = 0; kk < 16; kk++) {
            float a[4], b[4];
            #pragma unroll
            for (int u = 0; u < 4; u++) a[u] = As[kk][ty*4 + u];
            #pragma unroll
            for (int v = 0; v < 4; v++) b[v] = Bs[kk][tx*4 + v];
            #pragma unroll
            for (int u = 0; u < 4; u++)
                #pragma unroll
                for (int v = 0; v < 4; v++)
                    acc[u][v] += a[u] * b[v];
        }
        __syncthreads();
    }
    #pragma unroll
    for (int u = 0; u < 4; u++) {
        int m = m0 + ty*4 + u;
        int b = m >> 10, s = m & 1023;
        #pragma unroll
        for (int v = 0; v < 4; v++) {
            int n = n0 + tx*4 + v;
            int h = n >> 6, d = n & 63;
            C[(((b*NH + h) << 10) + s) * DK + d] = acc[u][v] + bias[n];
        }
    }
}

// ---- fused scores -> sigmoid -> threshold -> 32-draw Monte-Carlo sampler ----
// thresholds never leave registers; g_w receives the averaged draws; integer
// rowsums accumulate via atomics.
__global__ void k_scores_sampler() {
    __shared__ float Qs[64][65];
    __shared__ float Ks[64][65];
    __shared__ uint4 sk[NKEYS];
    int bh = blockIdx.z;
    int q0 = blockIdx.y * 64, c0 = blockIdx.x * 64;
    int tid = threadIdx.x, tx = tid & 15, ty = tid >> 4;
    if (tid < NKEYS) sk[tid] = g_keys[tid];
    const float* Qp = g_q + ((size_t)bh * SQ + q0) * DK;
    const float* Kp = g_k + ((size_t)bh * SQ + c0) * DK;
    for (int e = tid; e < 4096; e += 256) {
        int d = e & 63, r = e >> 6;
        Qs[d][r] = Qp[r * DK + d];
        Ks[d][r] = Kp[r * DK + d];
    }
    __syncthreads();
    float acc[4][4] = {};
    #pragma unroll 16
    for (int d = 0; d < 64; d++) {
        float a[4], b[4];
        #pragma unroll
        for (int u = 0; u < 4; u++) a[u] = Qs[d][ty*4 + u];
        #pragma unroll
        for (int v = 0; v < 4; v++) b[v] = Ks[d][tx*4 + v];
        #pragma unroll
        for (int u = 0; u < 4; u++)
            #pragma unroll
            for (int v = 0; v < 4; v++)
                acc[u][v] += a[u] * b[v];
    }
    // 4 rows per thread; 4 consecutive entries per row
    #pragma unroll 1
    for (int u = 0; u < 4; u++) {
        unsigned thr[4];
        #pragma unroll
        for (int v = 0; v < 4; v++) {
            float sc = acc[u][v] * 0.125f;          // 1/sqrt(64), BETA=1
            float p = 1.0f / (1.0f + expf(-sc));
            float tf = ceilf(p * 8388608.0f);        // p*2^23 exact in fp32
            thr[v] = (tf >= 8388608.0f) ? 0xFFFFFFFFu : (((unsigned)tf) << 9);
        }
        int row = (bh << 10) + q0 + ty*4 + u;
        unsigned i0 = ((unsigned)row << 10) + c0 + tx*4;
        unsigned n0c = 0u, n1c = 0u, n2c = 0u, n3c = 0u;
        #pragma unroll 1
        for (int j = 0; j < NKEYS; j++) {
            uint4 kk = sk[j];
            unsigned a0 = kk.x, a1 = i0 + kk.y;      // x0 = 0+k0 ; x1 = idx+k1
            unsigned b0 = kk.x, b1 = a1 + 1u;
            unsigned d0 = kk.x, d1 = a1 + 2u;
            unsigned e0 = kk.x, e1 = a1 + 3u;
            tf_block(a0, a1, kk.x, kk.y, kk.z);
            tf_block(b0, b1, kk.x, kk.y, kk.z);
            tf_block(d0, d1, kk.x, kk.y, kk.z);
            tf_block(e0, e1, kk.x, kk.y, kk.z);
            n0c += ((a0 ^ a1) < thr[0]) ? 1u : 0u;   // == (bits>>9)*2^-23 < p
            n1c += ((b0 ^ b1) < thr[1]) ? 1u : 0u;
            n2c += ((d0 ^ d1) < thr[2]) ? 1u : 0u;
            n3c += ((e0 ^ e1) < thr[3]) ? 1u : 0u;
        }
        atomicAdd(&g_rowsum[row], n0c + n1c + n2c + n3c);
        float4 out = make_float4(n0c * 0.03125f, n1c * 0.03125f,
                                 n2c * 0.03125f, n3c * 0.03125f);
        *(float4*)(g_w + i0) = out;                  // avg, exact multiple of 1/32
    }
}

// ---- per-row scale: 32/S == 1/(S/32) exactly (S integer < 2^24) ----
__global__ void k_recip() {
    int r = blockIdx.x * 256 + threadIdx.x;
    if (r < NROWS) {
        unsigned S = g_rowsum[r];
        g_scale[r] = (S > 0u) ? (32.0f / (float)S) : 0.0f;
    }
}

// ---- attn = (avg @ V) * (1/rowsum), per (b,h): 1024x64, K=1024 ----
__global__ void k_attn() {
    __shared__ float Ws[16][65];
    __shared__ float Vs[16][65];
    int bh = blockIdx.y;
    int q0 = blockIdx.x * 64;
    int tid = threadIdx.x, tx = tid & 15, ty = tid >> 4;
    int lr = tid >> 2, lc = (tid & 3) << 2;
    const float* wp = g_w + ((size_t)bh * SQ + q0) * SQ;
    const float* vp = g_v + (size_t)bh * SQ * DK;
    float acc[4][4] = {};
    for (int kc = 0; kc < SQ; kc += 16) {
        float4 a4 = *(const float4*)(wp + (size_t)lr * SQ + kc + lc);
        Ws[lc+0][lr] = a4.x; Ws[lc+1][lr] = a4.y; Ws[lc+2][lr] = a4.z; Ws[lc+3][lr] = a4.w;
        #pragma unroll
        for (int r = 0; r < 4; r++) {
            int ee = tid + r * 256;
            int d = ee & 63, kx = ee >> 6;
            Vs[kx][d] = vp[(size_t)(kc + kx) * DK + d];
        }
        __syncthreads();
        #pragma unroll
        for (int kk = 0; kk < 16; kk++) {
            float a[4], b[4];
            #pragma unroll
            for (int u = 0; u < 4; u++) a[u] = Ws[kk][ty*4 + u];
            #pragma unroll
            for (int v = 0; v < 4; v++) b[v] = Vs[kk][tx*4 + v];
            #pragma unroll
            for (int u = 0; u < 4; u++)
                #pragma unroll
                for (int v = 0; v < 4; v++)
                    acc[u][v] += a[u] * b[v];
        }
        __syncthreads();
    }
    #pragma unroll
    for (int u = 0; u < 4; u++) {
        int q = q0 + ty*4 + u;
        float sc = g_scale[bh * SQ + q];
        #pragma unroll
        for (int v = 0; v < 4; v++)
            g_attn[((size_t)bh * SQ + q) * DK + tx*4 + v] = acc[u][v] * sc;
    }
}

// ---- output projection: out = attn2d @ Wo^T + bo ----
__global__ void k_outp(const float* __restrict__ Wo, const float* __restrict__ bo,
                       float* __restrict__ out) {
    __shared__ float As[16][65];
    __shared__ float Bs[16][65];
    int tid = threadIdx.x;
    int tx = tid & 15, ty = tid >> 4;
    int m0 = blockIdx.y * 64, n0 = blockIdx.x * 64;
    int lr = tid >> 2;
    int lc = (tid & 3) << 2;
    float acc[4][4] = {};
    for (int kb = 0; kb < DM; kb += 16) {
        int m = m0 + lr;
        int c = kb + lc;
        int b = m >> 10, s = m & 1023, h = c >> 6, d = c & 63;
        float4 a4 = *(const float4*)(g_attn + ((size_t)((b*NH + h) << 10) + s) * DK + d);
        float4 b4 = *(const float4*)(Wo + (size_t)(n0 + lr) * DM + kb + lc);
        As[lc+0][lr] = a4.x; As[lc+1][lr] = a4.y; As[lc+2][lr] = a4.z; As[lc+3][lr] = a4.w;
        Bs[lc+0][lr] = b4.x; Bs[lc+1][lr] = b4.y; Bs[lc+2][lr] = b4.z; Bs[lc+3][lr] = b4.w;
        __syncthreads();
        #pragma unroll
        for (int kk = 0; kk < 16; kk++) {
            float a[4], b[4];
            #pragma unroll
            for (int u = 0; u < 4; u++) a[u] = As[kk][ty*4 + u];
            #pragma unroll
            for (int v = 0; v < 4; v++) b[v] = Bs[kk][tx*4 + v];
            #pragma unroll
            for (int u = 0; u < 4; u++)
                #pragma unroll
                for (int v = 0; v < 4; v++)
                    acc[u][v] += a[u] * b[v];
        }
        __syncthreads();
    }
    #pragma unroll
    for (int u = 0; u < 4; u++) {
        int m = m0 + ty*4 + u;
        #pragma unroll
        for (int v = 0; v < 4; v++) {
            int n = n0 + tx*4 + v;
            out[(size_t)m * DM + n] = acc[u][v] + bo[n];
        }
    }
}

extern "C" void kernel_launch(void* const* d_in, const int* in_sizes, int n_in,
                              void* d_out, int out_size) {
    const float* x  = (const float*)d_in[0];
    const float* Wq = (const float*)d_in[1];
    const float* bq = (const float*)d_in[2];
    const float* Wk = (const float*)d_in[3];
    const float* bk = (const float*)d_in[4];
    const float* Wv = (const float*)d_in[5];
    const float* bv = (const float*)d_in[6];
    const float* Wo = (const float*)d_in[7];
    const float* bo = (const float*)d_in[8];
    float* out = (float*)d_out;

    k_setup<<<96, 256>>>();

    dim3 gproj(DM / 64, (NB * SQ) / 64, 3);        // (12, 32, 3)
    k_qkv3<<<gproj, 256>>>(x, Wq, bq, Wk, bk, Wv, bv);

    dim3 gsc(SQ / 64, SQ / 64, NBH);               // (16, 16, 24)
    k_scores_sampler<<<gsc, 256>>>();

    k_recip<<<96, 256>>>();

    dim3 gat(SQ / 64, NBH);                        // (16, 24)
    k_attn<<<gat, 256>>>();

    dim3 gout(DM / 64, (NB * SQ) / 64);            // (12, 32)
    k_outp<<<gout, 256>>>(Wo, bo, out);
}